// round 17
// baseline (speedup 1.0000x reference)
#include <cuda_runtime.h>
#include <cuda_fp16.h>
#include <math.h>
#include <stdint.h>

// Problem constants
#define B_   16
#define N_   1024
#define D_   512
#define C_   4096
#define NTOT (B_ * N_)        // 16384
#define DECAY 0.8f
#define ONE_MINUS_DECAY 0.2f
#define EPS_ 1e-5f

// Output layout (floats), concatenated in reference return order
#define OFF_Q    0ull
#define OFF_IND  (OFF_Q + (unsigned long long)NTOT * D_)
#define OFF_DIST (OFF_IND + NTOT)
#define OFF_NE   (OFF_DIST + (unsigned long long)NTOT * C_)
#define OFF_NCS  (OFF_NE + (unsigned long long)C_ * D_)
#define OFF_NEA  (OFF_NCS + C_)

// GEMM tiling
#define BM 128
#define BN 256
#define BKF 32
#define NNT (C_ / BN)         // 16 n-tiles
#define NMT (NTOT / BM)       // 128 m-tiles

// ---------------------------------------------------------------------------
// Device scratch (static; no runtime allocation allowed)
// ---------------------------------------------------------------------------
__device__ float g_bins[C_];
__device__ float g_embed_sum[(size_t)C_ * D_];
__device__ float g_total;
__device__ float g_pmax[(size_t)NTOT * NNT];  // per-(row, ntile) approx max
// fp16 split operands (hi = rn(v), lo = rn(v - hi))
__device__ __align__(16) __half g_xh[(size_t)NTOT * D_];
__device__ __align__(16) __half g_xl[(size_t)NTOT * D_];
__device__ __align__(16) __half g_eh[(size_t)C_ * D_];
__device__ __align__(16) __half g_el[(size_t)C_ * D_];

// ---------------------------------------------------------------------------
// PTX helpers (base sm_80-level features only)
// ---------------------------------------------------------------------------
__device__ __forceinline__ uint32_t smem_u32(const void* p) {
    uint32_t a;
    asm("{ .reg .u64 t; cvta.to.shared.u64 t, %1; cvt.u32.u64 %0, t; }"
        : "=r"(a) : "l"(p));
    return a;
}
__device__ __forceinline__ void cp_async16(uint32_t dst, const void* src) {
    asm volatile("cp.async.ca.shared.global [%0], [%1], 16;"
                 :: "r"(dst), "l"(src) : "memory");
}
__device__ __forceinline__ void cp_commit() {
    asm volatile("cp.async.commit_group;" ::: "memory");
}
template <int N>
__device__ __forceinline__ void cp_wait() {
    asm volatile("cp.async.wait_group %0;" :: "n"(N) : "memory");
}
// m16n8k16 fp16 inputs, fp32 accumulate
__device__ __forceinline__ void mma_f16(float* d, const uint32_t* a,
                                        const uint32_t* b, const float* c) {
    asm volatile(
        "mma.sync.aligned.m16n8k16.row.col.f32.f16.f16.f32 "
        "{%0,%1,%2,%3}, {%4,%5,%6,%7}, {%8,%9}, {%10,%11,%12,%13};"
        : "=f"(d[0]), "=f"(d[1]), "=f"(d[2]), "=f"(d[3])
        : "r"(a[0]), "r"(a[1]), "r"(a[2]), "r"(a[3]),
          "r"(b[0]), "r"(b[1]),
          "f"(c[0]), "f"(c[1]), "f"(c[2]), "f"(c[3]));
}
// monotone float <-> uint encoding (for atomicMax on shared)
__device__ __forceinline__ unsigned fenc(float f) {
    unsigned u = __float_as_uint(f);
    return (u & 0x80000000u) ? ~u : (u | 0x80000000u);
}
__device__ __forceinline__ float fdec(unsigned u) {
    unsigned v = (u & 0x80000000u) ? (u & 0x7fffffffu) : ~u;
    return __uint_as_float(v);
}
__device__ __forceinline__ uint32_t pack2(float a, float b) {
    __half2 h = __floats2half2_rn(a, b);
    return *reinterpret_cast<uint32_t*>(&h);
}

// ---------------------------------------------------------------------------
// Kernel 1: fused prep (x/embed -> fp16 hi/lo splits) + scratch zeroing.
// Block partition: [0,XB) x | [XB,XB+EB) embed | rest zero.
// ---------------------------------------------------------------------------
#define XB (NTOT * D_ / 4 / 256)     // 8192
#define EB (C_ * D_ / 4 / 256)       // 2048
#define ZTOT ((C_ * D_ + C_) / 4)    // float4 count
#define ZB ((ZTOT + 255) / 256)      // 2053

__global__ __launch_bounds__(256)
void prep_zero_kernel(const float* __restrict__ x, const float* __restrict__ embed) {
    int b = blockIdx.x;
    if (b < XB + EB) {
        const float* src = (b < XB) ? x : embed;
        __half* dh = (b < XB) ? g_xh : g_eh;
        __half* dl = (b < XB) ? g_xl : g_el;
        size_t i = (size_t)(b < XB ? b : b - XB) * 256 + threadIdx.x;
        float4 v = reinterpret_cast<const float4*>(src)[i];
        __half h0 = __float2half_rn(v.x), h1 = __float2half_rn(v.y);
        __half h2 = __float2half_rn(v.z), h3 = __float2half_rn(v.w);
        float l0 = v.x - __half2float(h0), l1 = v.y - __half2float(h1);
        float l2 = v.z - __half2float(h2), l3 = v.w - __half2float(h3);
        uint2 hp, lp;
        hp.x = (uint32_t)__half_as_ushort(h0) | ((uint32_t)__half_as_ushort(h1) << 16);
        hp.y = (uint32_t)__half_as_ushort(h2) | ((uint32_t)__half_as_ushort(h3) << 16);
        lp.x = pack2(l0, l1);
        lp.y = pack2(l2, l3);
        reinterpret_cast<uint2*>(dh)[i] = hp;
        reinterpret_cast<uint2*>(dl)[i] = lp;
    } else {
        size_t i = (size_t)(b - XB - EB) * 256 + threadIdx.x;
        if (i < ZTOT) {
            float4 z = make_float4(0.f, 0.f, 0.f, 0.f);
            if (i < (size_t)C_ * D_ / 4)
                reinterpret_cast<float4*>(g_embed_sum)[i] = z;
            else
                reinterpret_cast<float4*>(g_bins)[i - (size_t)C_ * D_ / 4] = z;
        }
        if (b == XB + EB && threadIdx.x == 0) g_total = 0.0f;
    }
}

// ---------------------------------------------------------------------------
// Kernel 2: dist GEMM via mma.sync m16n8k16 fp16 split (hh + h*lo + lo*h).
// BM=128 BN=256 BK=32, 256 threads, warp grid 2x4, warp tile 64x64,
// 3-stage cp.async pipeline, fused per-(row, ntile) max -> g_pmax.
// Smem rows: 32 data halves + 8 pad = 40 halves (20 words); word-stride 20
// is conflict-free: (20g + q) distinct mod 32 over the warp.
// Stage layout (halves): A_hi[128*40] A_lo[128*40] B_hi[256*40] B_lo[256*40]
// ---------------------------------------------------------------------------
#define RS_H 40                               // halves per row
#define RS_W (RS_H / 2)                       // 20 words per row
#define AH_HALVES (BM * RS_H)                 // 5120
#define BH_HALVES (BN * RS_H)                 // 10240
#define STAGE_H (2 * AH_HALVES + 2 * BH_HALVES)  // 30720 halves = 61440 B
#define NSTAGE 3
#define SMEM_GEMM_BYTES (NSTAGE * STAGE_H * 2 + 512 + 128)

__global__ __launch_bounds__(256, 1)
void dist_mma_kernel(float* __restrict__ dist) {
    extern __shared__ char smem[];
    unsigned* smax = reinterpret_cast<unsigned*>(smem + NSTAGE * STAGE_H * 2);
    const uint32_t sbase = smem_u32(smem);
    const int tid = threadIdx.x;
    const int wid = tid >> 5;
    const int lane = tid & 31;
    const int g = lane >> 2;   // 0..7
    const int q = lane & 3;    // 0..3
    const int wm = (wid >> 2) * 64;  // warp m offset (2 warps in m)
    const int wn = (wid & 3) * 64;   // warp n offset (4 warps in n)

    const int ntile = blockIdx.x;
    const int mtile = blockIdx.y;
    const int m0 = mtile * BM;
    const int c0 = ntile * BN;

    if (tid < BM) smax[tid] = 0u;   // enc(-inf) < any enc

    float acc[4][8][4];
#pragma unroll
    for (int mt = 0; mt < 4; mt++)
#pragma unroll
        for (int nt = 0; nt < 8; nt++)
#pragma unroll
            for (int j = 0; j < 4; j++) acc[mt][nt][j] = 0.0f;

    // stage load: each 16B chunk = 8 halves; row = 4 chunks (64B data)
    auto load_stage = [&](int kt, int st) {
        const uint32_t s0 = sbase + (uint32_t)(st * STAGE_H) * 2;
        const uint32_t ah = s0;
        const uint32_t al = s0 + AH_HALVES * 2;
        const uint32_t bh = s0 + 2 * AH_HALVES * 2;
        const uint32_t bl = bh + BH_HALVES * 2;
        // A: 128 rows x 4 chunks = 512 chunks, 2/thread (hi and lo each)
#pragma unroll
        for (int l = 0; l < 2; l++) {
            int idx = tid + l * 256;
            int row = idx >> 2;
            int ch = idx & 3;
            uint32_t doff = (uint32_t)(row * RS_H + ch * 8) * 2;
            size_t soff = (size_t)(m0 + row) * D_ + kt * BKF + ch * 8;
            cp_async16(ah + doff, &g_xh[soff]);
            cp_async16(al + doff, &g_xl[soff]);
        }
        // B: 256 rows x 4 chunks = 1024 chunks, 4/thread (hi and lo each)
#pragma unroll
        for (int l = 0; l < 4; l++) {
            int idx = tid + l * 256;
            int row = idx >> 2;
            int ch = idx & 3;
            uint32_t doff = (uint32_t)(row * RS_H + ch * 8) * 2;
            size_t soff = (size_t)(c0 + row) * D_ + kt * BKF + ch * 8;
            cp_async16(bh + doff, &g_eh[soff]);
            cp_async16(bl + doff, &g_el[soff]);
        }
        cp_commit();
    };

    load_stage(0, 0);
    load_stage(1, 1);

    const int NK = D_ / BKF;   // 16
    for (int kt = 0; kt < NK; kt++) {
        if (kt + 1 < NK) cp_wait<1>(); else cp_wait<0>();
        __syncthreads();
        if (kt + 2 < NK) load_stage(kt + 2, (kt + 2) % NSTAGE);

        const int st = kt % NSTAGE;
        const uint32_t* S = reinterpret_cast<const uint32_t*>(smem) + st * (STAGE_H / 2);
        const uint32_t* AuH = S;
        const uint32_t* AuL = S + AH_HALVES / 2;
        const uint32_t* BuH = S + AH_HALVES;           // 2*AH_HALVES halves = AH_HALVES words
        const uint32_t* BuL = BuH + BH_HALVES / 2;

#pragma unroll
        for (int ks = 0; ks < 2; ks++) {               // two k16 slabs per BK=32
            const int w0 = ks * 8;                     // word offset within row
            uint32_t ah[4][4], al[4][4], bhf[8][2], blf[8][2];
#pragma unroll
            for (int mt = 0; mt < 4; mt++) {
                int r = (wm + mt * 16 + g) * RS_W;
                int r8 = r + 8 * RS_W;
                ah[mt][0] = AuH[r + w0 + q];
                ah[mt][1] = AuH[r8 + w0 + q];
                ah[mt][2] = AuH[r + w0 + 4 + q];
                ah[mt][3] = AuH[r8 + w0 + 4 + q];
                al[mt][0] = AuL[r + w0 + q];
                al[mt][1] = AuL[r8 + w0 + q];
                al[mt][2] = AuL[r + w0 + 4 + q];
                al[mt][3] = AuL[r8 + w0 + 4 + q];
            }
#pragma unroll
            for (int nt = 0; nt < 8; nt++) {
                int rn = (wn + nt * 8 + g) * RS_W;
                bhf[nt][0] = BuH[rn + w0 + q];
                bhf[nt][1] = BuH[rn + w0 + 4 + q];
                blf[nt][0] = BuL[rn + w0 + q];
                blf[nt][1] = BuL[rn + w0 + 4 + q];
            }
#pragma unroll
            for (int mt = 0; mt < 4; mt++)
#pragma unroll
                for (int nt = 0; nt < 8; nt++) {
                    mma_f16(acc[mt][nt], ah[mt], bhf[nt], acc[mt][nt]);  // hh
                    mma_f16(acc[mt][nt], ah[mt], blf[nt], acc[mt][nt]);  // h*lo
                    mma_f16(acc[mt][nt], al[mt], bhf[nt], acc[mt][nt]);  // lo*h
                }
        }
    }
    __syncthreads();

    // Epilogue: write dist + per-row max (shared atomicMax, enc monotone)
#pragma unroll
    for (int mt = 0; mt < 4; mt++) {
        float mA = -INFINITY, mB = -INFINITY;
#pragma unroll
        for (int nt = 0; nt < 8; nt++) {
            int row = m0 + wm + mt * 16 + g;
            int col = c0 + wn + nt * 8 + 2 * q;
            float2 v01 = make_float2(acc[mt][nt][0], acc[mt][nt][1]);
            float2 v23 = make_float2(acc[mt][nt][2], acc[mt][nt][3]);
            *reinterpret_cast<float2*>(&dist[(size_t)row * C_ + col]) = v01;
            *reinterpret_cast<float2*>(&dist[(size_t)(row + 8) * C_ + col]) = v23;
            mA = fmaxf(mA, fmaxf(v01.x, v01.y));
            mB = fmaxf(mB, fmaxf(v23.x, v23.y));
        }
        atomicMax(&smax[wm + mt * 16 + g], fenc(mA));
        atomicMax(&smax[wm + mt * 16 + 8 + g], fenc(mB));
    }
    __syncthreads();
    if (tid < BM)
        g_pmax[(size_t)(m0 + tid) * NNT + ntile] = fdec(smax[tid]);
}

// ---------------------------------------------------------------------------
// Kernel 3: rescue argmax driven by tile maxes + exact recompute of
//           near-max candidates + gather quantize + scatter embed_sum/bins.
// One block per row n, 128 threads.
// ---------------------------------------------------------------------------
#define MARGIN 3e-3f
#define MAXCAND 32

__global__ __launch_bounds__(128)
void rescue_kernel(const float* __restrict__ dist,
                   const float* __restrict__ x,
                   const float* __restrict__ embed,
                   float* __restrict__ quant_out,
                   float* __restrict__ ind_out) {
    const int n = blockIdx.x;
    const int tid = threadIdx.x;
    __shared__ float spm[NNT];
    __shared__ float sred[128];
    __shared__ int scand[MAXCAND];
    __shared__ int scount;
    __shared__ float sM;
    __shared__ float sbest;
    __shared__ int sbidx;

    if (tid < NNT) spm[tid] = g_pmax[(size_t)n * NNT + tid];
    if (tid == 0) { scount = 0; sbest = -INFINITY; sbidx = 0; }
    __syncthreads();
    if (tid == 0) {
        float M = -INFINITY;
#pragma unroll
        for (int t = 0; t < NNT; t++) M = fmaxf(M, spm[t]);
        sM = M;
    }
    __syncthreads();
    const float thresh = sM - MARGIN;

    const float* drow = dist + (size_t)n * C_;
#pragma unroll 1
    for (int t = 0; t < NNT; t++) {
        if (spm[t] >= thresh) {
#pragma unroll
            for (int i = 0; i < 2; i++) {
                int c = t * BN + i * 128 + tid;
                if (drow[c] >= thresh) {
                    int p = atomicAdd(&scount, 1);
                    if (p < MAXCAND) scand[p] = c;
                }
            }
        }
    }
    __syncthreads();
    int ncand = min(scount, MAXCAND);
    if (tid == 0 && ncand > 1) {
        // insertion sort ascending (first-index tie-break like jnp.argmax)
        for (int i = 1; i < ncand; i++) {
            int key = scand[i];
            int j = i - 1;
            while (j >= 0 && scand[j] > key) { scand[j + 1] = scand[j]; j--; }
            scand[j + 1] = key;
        }
    }
    __syncthreads();

    const float4 x4v = reinterpret_cast<const float4*>(x + (size_t)n * D_)[tid];

    for (int ci = 0; ci < ncand; ci++) {
        const int c = scand[ci];
        const float4 e4 = reinterpret_cast<const float4*>(embed + (size_t)c * D_)[tid];
        float p = x4v.x * e4.x + x4v.y * e4.y + x4v.z * e4.z + x4v.w * e4.w;
        sred[tid] = p;
        __syncthreads();
#pragma unroll
        for (int s = 64; s > 0; s >>= 1) {
            if (tid < s) sred[tid] += sred[tid + s];
            __syncthreads();
        }
        if (tid == 0) {
            float v = sred[0];
            if (v > sbest) { sbest = v; sbidx = c; }  // ascending ci keeps lowest idx on tie
        }
        __syncthreads();
    }

    const int ind = sbidx;
    if (tid == 0) {
        ind_out[n] = (float)ind;
        atomicAdd(&g_bins[ind], 1.0f);
    }

    const float4 e4 = reinterpret_cast<const float4*>(embed + (size_t)ind * D_)[tid];
    reinterpret_cast<float4*>(quant_out + (size_t)n * D_)[tid] = e4;
    float* srowp = g_embed_sum + (size_t)ind * D_ + tid * 4;
    atomicAdd(&srowp[0], x4v.x);
    atomicAdd(&srowp[1], x4v.y);
    atomicAdd(&srowp[2], x4v.z);
    atomicAdd(&srowp[3], x4v.w);
}

// ---------------------------------------------------------------------------
// Kernel 4: new_cluster_size + total (parallel; g_total pre-zeroed)
// ---------------------------------------------------------------------------
__global__ __launch_bounds__(256)
void cluster_size_kernel(const float* __restrict__ cluster_size,
                         float* __restrict__ ncs_out) {
    const int base = blockIdx.x * 1024 + threadIdx.x * 4;
    float4 cs = *reinterpret_cast<const float4*>(&cluster_size[base]);
    float4 bn = *reinterpret_cast<const float4*>(&g_bins[base]);
    float4 v;
    v.x = cs.x * DECAY + bn.x * ONE_MINUS_DECAY;
    v.y = cs.y * DECAY + bn.y * ONE_MINUS_DECAY;
    v.z = cs.z * DECAY + bn.z * ONE_MINUS_DECAY;
    v.w = cs.w * DECAY + bn.w * ONE_MINUS_DECAY;
    *reinterpret_cast<float4*>(&ncs_out[base]) = v;
    float local = v.x + v.y + v.z + v.w;

    __shared__ float red[256];
    red[threadIdx.x] = local;
    __syncthreads();
#pragma unroll
    for (int s = 128; s > 0; s >>= 1) {
        if (threadIdx.x < s) red[threadIdx.x] += red[threadIdx.x + s];
        __syncthreads();
    }
    if (threadIdx.x == 0) atomicAdd(&g_total, red[0]);
}

// ---------------------------------------------------------------------------
// Kernel 5: per-code EMA + normalize. One block per code c, 128 threads,
// float4 vectorized, shuffle+smem reduction.
// ---------------------------------------------------------------------------
__global__ __launch_bounds__(128)
void embed_update_kernel(const float* __restrict__ embed_avg,
                         const float* __restrict__ ncs,
                         float* __restrict__ nea_out,
                         float* __restrict__ ne_out) {
    const int c = blockIdx.x;
    const int tid = threadIdx.x;

    const float total = g_total;
    const float n_cs = ncs[c];
    const float smoothed = (n_cs + EPS_) / (total + (float)C_ * EPS_) * total;
    const float inv_s = 1.0f / smoothed;

    const float4 ea = reinterpret_cast<const float4*>(embed_avg + (size_t)c * D_)[tid];
    const float4 es = reinterpret_cast<const float4*>(g_embed_sum + (size_t)c * D_)[tid];
    float4 nea;
    nea.x = ea.x * DECAY + es.x * ONE_MINUS_DECAY;
    nea.y = ea.y * DECAY + es.y * ONE_MINUS_DECAY;
    nea.z = ea.z * DECAY + es.z * ONE_MINUS_DECAY;
    nea.w = ea.w * DECAY + es.w * ONE_MINUS_DECAY;
    reinterpret_cast<float4*>(nea_out + (size_t)c * D_)[tid] = nea;

    float4 t;
    t.x = nea.x * inv_s; t.y = nea.y * inv_s;
    t.z = nea.z * inv_s; t.w = nea.w * inv_s;
    float sumsq = t.x * t.x + t.y * t.y + t.z * t.z + t.w * t.w;

#pragma unroll
    for (int o = 16; o > 0; o >>= 1)
        sumsq += __shfl_xor_sync(0xFFFFFFFFu, sumsq, o);
    __shared__ float wred[4];
    if ((tid & 31) == 0) wred[tid >> 5] = sumsq;
    __syncthreads();
    float tot = wred[0] + wred[1] + wred[2] + wred[3];

    float norm = fmaxf(sqrtf(tot), 1e-12f);
    float inv_n = 1.0f / norm;
    float4 o4;
    o4.x = t.x * inv_n; o4.y = t.y * inv_n;
    o4.z = t.z * inv_n; o4.w = t.w * inv_n;
    reinterpret_cast<float4*>(ne_out + (size_t)c * D_)[tid] = o4;
}

// ---------------------------------------------------------------------------
// Launch
// ---------------------------------------------------------------------------
extern "C" void kernel_launch(void* const* d_in, const int* in_sizes, int n_in,
                              void* d_out, int out_size) {
    const float* x          = (const float*)d_in[0];  // (16,1024,512)
    const float* embed      = (const float*)d_in[1];  // (1,4096,512)
    const float* cluster_sz = (const float*)d_in[2];  // (1,4096)
    const float* embed_avg  = (const float*)d_in[3];  // (1,4096,512)
    float* out = (float*)d_out;

    float* out_q    = out + OFF_Q;
    float* out_ind  = out + OFF_IND;
    float* out_dist = out + OFF_DIST;
    float* out_ne   = out + OFF_NE;
    float* out_ncs  = out + OFF_NCS;
    float* out_nea  = out + OFF_NEA;

    (void)in_sizes; (void)n_in; (void)out_size;

    prep_zero_kernel<<<XB + EB + ZB, 256>>>(x, embed);

    static bool attr_done = false;
    if (!attr_done) {
        cudaFuncSetAttribute(dist_mma_kernel,
                             cudaFuncAttributeMaxDynamicSharedMemorySize,
                             SMEM_GEMM_BYTES);
        attr_done = true;
    }
    dim3 ggrid(NNT, NMT);   // (16, 128)
    dist_mma_kernel<<<ggrid, 256, SMEM_GEMM_BYTES>>>(out_dist);

    rescue_kernel<<<NTOT, 128>>>(out_dist, x, embed, out_q, out_ind);

    cluster_size_kernel<<<4, 256>>>(cluster_sz, out_ncs);

    embed_update_kernel<<<C_, 128>>>(embed_avg, out_ncs, out_nea, out_ne);
}